// round 9
// baseline (speedup 1.0000x reference)
#include <cuda_runtime.h>
#include <math.h>

#define DAYS  365
#define NY    30
#define SGRID 4000
#define TT    (DAYS * NY)
#define NPAIR 435
#define NQ    5
#define K1_SER 32
#define SROW  369            // smem row stride (floats); row needs 368; 369%32=17 (odd)

#define POSINF __int_as_float(0x7f800000)
#define FULLM  0xffffffffu

// ---------------- intermediate storage (no allocations allowed) -------------
__device__ float  g_pM[SGRID * NY];
__device__ float  g_tM[SGRID * NY];
__device__ float  g_pQ[SGRID * NQ * NY];
__device__ float  g_tQ[SGRID * NQ * NY];
__device__ double g_sse;
__device__ double g_trend;
__device__ int    g_pairIJ[NPAIR];   // i | (j<<8)
__device__ float  g_pairInv[NPAIR];  // 1/(j-i)

// compile-time-direction comparator: a <- min, b <- max (2 FMNMX)
__device__ __forceinline__ void cswapF(float& a, float& b) {
    float lo = fminf(a, b), hi = fmaxf(a, b); a = lo; b = hi;
}

// ============ 384-slot pruned bitonic, 24 regs, TWO series per warp ==========
// Slot g (9 bits): {g0,g1,g2} -> reg lo3, {g3..g6} -> lane4 (lane&15),
// {g7,g8} -> reg hi2 (hi2==3 virtual/pruned). r = lo3 | (hi2<<3), 0..23.
// lane bit 4 selects which of the two series this half-warp sorts.
// 528 FMNMX + 232 SHFL per warp-walk (serves 2 series).

__device__ __forceinline__ void P1(float v[24]) {
#pragma unroll
    for (int r = 0; r < 24; r++) if ((r & 1) == 0) cswapF(v[r], v[r | 1]);
}
__device__ __forceinline__ void P2(float v[24]) {
#pragma unroll
    for (int r = 0; r < 24; r++) if ((r & 2) == 0) cswapF(v[r], v[r | 2]);
}
__device__ __forceinline__ void P4(float v[24]) {
#pragma unroll
    for (int r = 0; r < 24; r++) if ((r & 4) == 0) cswapF(v[r], v[r | 4]);
}
__device__ __forceinline__ void F3(float v[24]) {
#pragma unroll
    for (int r = 0; r < 24; r++) if ((r & 3) < 2) cswapF(v[r], v[r ^ 3]);
}
__device__ __forceinline__ void F7(float v[24]) {
#pragma unroll
    for (int r = 0; r < 24; r++) if ((r & 7) < 4) cswapF(v[r], v[r ^ 7]);
}
__device__ __forceinline__ void P128(float v[24]) {   // hi2 0<->1; 2<->3 pruned
#pragma unroll
    for (int r = 0; r < 8; r++) cswapF(v[r], v[r + 8]);
}
// plain cross-lane substage: global stride 8*lm, lm in {1,2,4,8}
__device__ __forceinline__ void CR(float v[24], int lane, int lm) {
    bool kp = (lane & lm) == 0;
#pragma unroll
    for (int r = 0; r < 24; r++) {
        float o = __shfl_xor_sync(FULLM, v[r], lm);
        v[r] = kp ? fminf(v[r], o) : fmaxf(v[r], o);
    }
}
// flip substage k=16..128: partner reg = r^7 (same octet), partner lane ^lmc.
// Processed per octet: <=8 temps live, reads always pre-update (octets disjoint).
__device__ __forceinline__ void FL(float v[24], int lane, int lmc, int pb) {
    bool kp = (lane & pb) == 0;
#pragma unroll
    for (int oct = 0; oct < 24; oct += 8) {
        float t[8];
#pragma unroll
        for (int i = 0; i < 8; i++) t[i] = __shfl_xor_sync(FULLM, v[oct + (i ^ 7)], lmc);
#pragma unroll
        for (int i = 0; i < 8; i++) v[oct + i] = kp ? fminf(v[oct + i], t[i])
                                                    : fmaxf(v[oct + i], t[i]);
    }
}
// flip k=256: pairs (r, 15-r), lane^15; hi2=2 partners virtual (pruned).
// Two reg-disjoint groups: {0-3,12-15} then {4-11}.
__device__ __forceinline__ void F256(float v[24]) {
#pragma unroll
    for (int h = 0; h < 2; h++) {
        int base = h ? 4 : 0;           // pairs i=base..base+3
        float t1[4], t2[4];
#pragma unroll
        for (int i = 0; i < 4; i++) {
            t1[i] = __shfl_xor_sync(FULLM, v[15 - (base + i)], 15);
            t2[i] = __shfl_xor_sync(FULLM, v[base + i], 15);
        }
#pragma unroll
        for (int i = 0; i < 4; i++) {
            v[base + i]        = fminf(v[base + i], t1[i]);
            v[15 - (base + i)] = fmaxf(v[15 - (base + i)], t2[i]);
        }
    }
}
// flip k=512: pairs (r, 31-r) for r=8..15, lane^15; r=0..7 partners virtual.
// Groups: {8-11,20-23} then {12-19}.
__device__ __forceinline__ void F512(float v[24]) {
#pragma unroll
    for (int h = 0; h < 2; h++) {
        int base = h ? 12 : 8;
        float t1[4], t2[4];
#pragma unroll
        for (int i = 0; i < 4; i++) {
            t1[i] = __shfl_xor_sync(FULLM, v[31 - (base + i)], 15);
            t2[i] = __shfl_xor_sync(FULLM, v[base + i], 15);
        }
#pragma unroll
        for (int i = 0; i < 4; i++) {
            v[base + i]        = fminf(v[base + i], t1[i]);
            v[31 - (base + i)] = fmaxf(v[31 - (base + i)], t2[i]);
        }
    }
}

__device__ __forceinline__ void bsort384h(float v[24], int lane) {
    P1(v);                                                   // k=2
    F3(v); P1(v);                                            // k=4
    F7(v); P2(v); P1(v);                                     // k=8
    FL(v, lane, 1, 1);  P4(v); P2(v); P1(v);                 // k=16
    FL(v, lane, 3, 2);  CR(v, lane, 1); P4(v); P2(v); P1(v); // k=32
    FL(v, lane, 7, 4);  CR(v, lane, 2); CR(v, lane, 1);
    P4(v); P2(v); P1(v);                                     // k=64
    FL(v, lane, 15, 8); CR(v, lane, 4); CR(v, lane, 2); CR(v, lane, 1);
    P4(v); P2(v); P1(v);                                     // k=128
    F256(v); CR(v, lane, 8); CR(v, lane, 4); CR(v, lane, 2); CR(v, lane, 1);
    P4(v); P2(v); P1(v);                                     // k=256
    F512(v); P128(v); CR(v, lane, 8); CR(v, lane, 4); CR(v, lane, 2);
    CR(v, lane, 1); P4(v); P2(v); P1(v);                     // k=512
}

// ================= full 512 sorter (lane-major, for k_theil) =================
__device__ __forceinline__ void bsort512(float v[16], int lane) {
#pragma unroll
    for (int k = 2; k <= 16; k <<= 1) {
#pragma unroll
        for (int r = 0; r < 16; r++)
            if ((r & (k - 1)) < (k >> 1)) cswapF(v[r], v[r ^ (k - 1)]);
#pragma unroll
        for (int j = 8; j >= 1; j >>= 1)
            if (j <= (k >> 2)) {
#pragma unroll
                for (int r = 0; r < 16; r++)
                    if ((r & j) == 0) cswapF(v[r], v[r | j]);
            }
    }
#pragma unroll
    for (int k = 32; k <= 512; k <<= 1) {
        {
            int  lm      = (k - 1) >> 4;
            bool keepmin = ((lane & (k >> 5)) == 0);
#pragma unroll
            for (int r = 0; r < 8; r++) {
                float a = __shfl_xor_sync(FULLM, v[15 - r], lm);
                float b = __shfl_xor_sync(FULLM, v[r], lm);
                v[r]      = keepmin ? fminf(v[r], a)      : fmaxf(v[r], a);
                v[15 - r] = keepmin ? fminf(v[15 - r], b) : fmaxf(v[15 - r], b);
            }
        }
#pragma unroll
        for (int j = 128; j >= 16; j >>= 1)
            if (j <= (k >> 2)) {
                int  lm      = j >> 4;
                bool keepmin = ((lane & lm) == 0);
#pragma unroll
                for (int r = 0; r < 16; r++) {
                    float o = __shfl_xor_sync(FULLM, v[r], lm);
                    v[r] = keepmin ? fminf(v[r], o) : fmaxf(v[r], o);
                }
            }
#pragma unroll
        for (int j = 8; j >= 1; j >>= 1) {
#pragma unroll
            for (int r = 0; r < 16; r++)
                if ((r & j) == 0) cswapF(v[r], v[r | j]);
        }
    }
}

// ---------------- kernel 0: zero accumulators + build pair tables ------------
__global__ void k_zero() {
    int tid = threadIdx.x;
    if (tid == 0) { g_sse = 0.0; g_trend = 0.0; }
    if (tid < NPAIR) {
        int i = 0, rem = tid, cnt = NY - 1;
        while (rem >= cnt) { rem -= cnt; i++; cnt--; }
        int j = i + 1 + rem;
        g_pairIJ[tid]  = i | (j << 8);
        g_pairInv[tid] = 1.0f / (float)(j - i);
    }
}

// ---------------- kernel 1: transpose + SSE + per-(series,year) sort ---------
// grid (SGRID/32, NY), block 512 (16 warps; each warp sorts 2 series per pass)
// dynamic smem: shP[32][SROW], shT[32][SROW]  (94,464 B)
__global__ __launch_bounds__(512, 2) void k_sortdays(const float* __restrict__ pred,
                                                     const float* __restrict__ obs) {
    extern __shared__ float dsm[];
    float* shP = dsm;                       // [32][SROW]
    float* shT = dsm + K1_SER * SROW;       // [32][SROW]
    __shared__ float warpsum[16];

    int y      = blockIdx.y;
    int s_base = blockIdx.x * K1_SER;
    int tid    = threadIdx.x;
    int w      = tid >> 5;
    int lane   = tid & 31;
    int lane4  = lane & 15;

    const float* pbase = pred + (size_t)y * DAYS * SGRID + s_base;
    const float* tbase = obs  + (size_t)y * DAYS * SGRID + s_base;

    // vectorized coalesced load (full 128B lines) + transpose + fused SSE
    // day d -> smem col (d&7)*46 + (d>>3)
    float sse = 0.0f;
    for (int idx = tid; idx < DAYS * (K1_SER / 4); idx += 512) {
        int d  = idx >> 3;
        int sv = (idx & 7) << 2;
        int ad = (d & 7) * 46 + (d >> 3);
        float4 a4 = *(const float4*)(pbase + d * SGRID + sv);
        float4 b4 = *(const float4*)(tbase + d * SGRID + sv);
        shP[(sv + 0) * SROW + ad] = a4.x;  shT[(sv + 0) * SROW + ad] = b4.x;
        shP[(sv + 1) * SROW + ad] = a4.y;  shT[(sv + 1) * SROW + ad] = b4.y;
        shP[(sv + 2) * SROW + ad] = a4.z;  shT[(sv + 2) * SROW + ad] = b4.z;
        shP[(sv + 3) * SROW + ad] = a4.w;  shT[(sv + 3) * SROW + ad] = b4.w;
        float dx = a4.x - b4.x, dy = a4.y - b4.y;
        float dz = a4.z - b4.z, dw = a4.w - b4.w;
        sse += dx * dx + dy * dy + dz * dz + dw * dw;
    }
#pragma unroll
    for (int o = 16; o > 0; o >>= 1) sse += __shfl_down_sync(FULLM, sse, o);
    if (lane == 0) warpsum[w] = sse;
    __syncthreads();
    if (tid == 0) {
        float tot = 0.0f;
#pragma unroll
        for (int i = 0; i < 16; i++) tot += warpsum[i];
        atomicAdd(&g_sse, (double)tot);
    }

    // this half-warp's series
    int sidx = 2 * w + (lane >> 4);     // 0..31 within block
    int s    = s_base + sidx;
    const float* rowP = shP + sidx * SROW;
    const float* rowT = shT + sidx * SROW;

#pragma unroll 1
    for (int pass = 0; pass < 2; pass++) {
        const float* row = pass ? rowT : rowP;
        float* outM = pass ? g_tM : g_pM;
        float* outQ = pass ? g_tQ : g_pQ;

        // load: reg r holds slot g = (r&7) | (lane4<<3) | ((r>>3)<<7)
        float v[24];
        float msum = 0.0f;
#pragma unroll
        for (int r = 0; r < 24; r++) {
            int lo3 = r & 7, hi2 = r >> 3;
            int g   = lo3 | (lane4 << 3) | (hi2 << 7);
            if (g < DAYS) { v[r] = row[lo3 * 46 + lane4 + (hi2 << 4)]; msum += v[r]; }
            else          { v[r] = POSINF; }
        }
        // per-half mean (xor butterfly within 16-lane half)
#pragma unroll
        for (int o = 8; o > 0; o >>= 1) msum += __shfl_xor_sync(FULLM, msum, o);
        if (lane4 == 0) outM[s * NY + y] = msum / (float)DAYS;

        bsort384h(v, lane);

        // rank R -> reg (R&7)|((R>>7)<<3), lane4 (R>>3)&15
        if (lane4 == 13) {
            outQ[(s * NQ + 0) * NY + y] = v[20];  // rank 364
            outQ[(s * NQ + 3) * NY + y] = v[5];   // rank 109
        }
        if (lane4 == 12) outQ[(s * NQ + 1) * NY + y] = v[21];  // rank 357
        if (lane4 == 6)  outQ[(s * NQ + 2) * NY + y] = v[14];  // rank 182
        if (lane4 == 0)  outQ[(s * NQ + 4) * NY + y] = v[7];   // rank 7
    }
}

// ---------------- kernel 2: Theil-Sen medians + trend terms ------------------
// grid SGRID, block 192 (6 warps: warp0 = mean, warps 1..5 = quantiles)
__global__ __launch_bounds__(192) void k_theil() {
    __shared__ float xs[6][2][NY];

    int s    = blockIdx.x;
    int w    = threadIdx.x >> 5;
    int lane = threadIdx.x & 31;

    const float* xp;
    const float* xt;
    if (w == 0) { xp = g_pM + s * NY;                  xt = g_tM + s * NY; }
    else        { xp = g_pQ + (s * NQ + (w - 1)) * NY; xt = g_tQ + (s * NQ + (w - 1)) * NY; }
    if (lane < NY) {
        xs[w][0][lane] = xp[lane];
        xs[w][1][lane] = xt[lane];
    }
    __syncwarp();

    float med[2];
#pragma unroll 1
    for (int pass = 0; pass < 2; pass++) {
        float v[16];
#pragma unroll
        for (int r = 0; r < 16; r++) {
            int p = (r << 5) | lane;   // arbitrary pair->slot map (median is set-invariant)
            if (p < NPAIR) {
                int   ij  = g_pairIJ[p];
                float inv = g_pairInv[p];
                int i = ij & 255, j = ij >> 8;
                v[r] = (xs[w][pass][j] - xs[w][pass][i]) * inv;
            } else {
                v[r] = POSINF;
            }
        }
        bsort512(v, lane);
        // median of 435 = sorted element 217 -> lane 13, reg 9 (lane-major)
        med[pass] = __shfl_sync(FULLM, v[9], 13);
    }

    if (lane == 0) {
        float sp = med[0], st = med[1];
        double term;
        if (w == 0) { float d = st - sp;   term = (double)d * (double)d; }
        else        { float q = st / (-sp); term = (double)q * (double)q; }
        atomicAdd(&g_trend, term);
    }
}

// ---------------- kernel 3: finalize -----------------------------------------
__global__ void k_final(float* out) {
    double mse = g_sse / ((double)TT * (double)SGRID);
    out[0] = (float)(sqrt(mse) + g_trend / (double)SGRID);
}

// ---------------- launch ------------------------------------------------------
extern "C" void kernel_launch(void* const* d_in, const int* in_sizes, int n_in,
                              void* d_out, int out_size) {
    const float* y_pred = (const float*)d_in[0];
    const float* y_obs  = (const float*)d_in[1];
    float* out = (float*)d_out;

    const int dyn_smem = 2 * K1_SER * SROW * (int)sizeof(float);  // 94,464 B
    cudaFuncSetAttribute(k_sortdays, cudaFuncAttributeMaxDynamicSharedMemorySize,
                         dyn_smem);

    k_zero<<<1, 512>>>();
    k_sortdays<<<dim3(SGRID / K1_SER, NY), 512, dyn_smem>>>(y_pred, y_obs);
    k_theil<<<SGRID, 192>>>();
    k_final<<<1, 1>>>(out);
}

// round 10
// speedup vs baseline: 1.0533x; 1.0533x over previous
#include <cuda_runtime.h>
#include <math.h>

#define DAYS  365
#define NY    30
#define SGRID 4000
#define TT    (DAYS * NY)
#define NPAIR 435
#define NQ    5
#define K1_SER 16
#define SROW  369            // smem row stride (floats); row needs 368

#define POSINF __int_as_float(0x7f800000)
#define FULLM  0xffffffffu

// ---------------- intermediate storage (no allocations allowed) -------------
__device__ float  g_pM[SGRID * NY];
__device__ float  g_tM[SGRID * NY];
__device__ float  g_pQ[SGRID * NQ * NY];
__device__ float  g_tQ[SGRID * NQ * NY];
__device__ double g_sse;
__device__ double g_trend;
__device__ int    g_pairIJ[NPAIR];   // i | (j<<8)
__device__ float  g_pairInv[NPAIR];  // 1/(j-i)

// compile-time-direction comparator: a <- min, b <- max (2 FMNMX)
__device__ __forceinline__ void cswapF(float& a, float& b) {
    float lo = fminf(a, b), hi = fmaxf(a, b); a = lo; b = hi;
}

// ============ 384-slot pruned bitonic, 24 regs, TWO series per warp ==========
// Slot g (9 bits): {g0,g1,g2} -> reg lo3, {g3..g6} -> lane4 (lane&15),
// {g7,g8} -> reg hi2 (hi2==3 virtual/pruned). r = lo3 | (hi2<<3), 0..23.
// lane bit 4 selects which of the two series this half-warp sorts.
// 1056 FMNMX + 464 SHFL per warp-walk (serves 2 series).

__device__ __forceinline__ void P1(float v[24]) {
#pragma unroll
    for (int r = 0; r < 24; r++) if ((r & 1) == 0) cswapF(v[r], v[r | 1]);
}
__device__ __forceinline__ void P2(float v[24]) {
#pragma unroll
    for (int r = 0; r < 24; r++) if ((r & 2) == 0) cswapF(v[r], v[r | 2]);
}
__device__ __forceinline__ void P4(float v[24]) {
#pragma unroll
    for (int r = 0; r < 24; r++) if ((r & 4) == 0) cswapF(v[r], v[r | 4]);
}
__device__ __forceinline__ void F3(float v[24]) {
#pragma unroll
    for (int r = 0; r < 24; r++) if ((r & 3) < 2) cswapF(v[r], v[r ^ 3]);
}
__device__ __forceinline__ void F7(float v[24]) {
#pragma unroll
    for (int r = 0; r < 24; r++) if ((r & 7) < 4) cswapF(v[r], v[r ^ 7]);
}
__device__ __forceinline__ void P128(float v[24]) {   // hi2 0<->1; 2<->3 pruned
#pragma unroll
    for (int r = 0; r < 8; r++) cswapF(v[r], v[r + 8]);
}
// plain cross-lane substage: global stride 8*lm, lm in {1,2,4,8}
__device__ __forceinline__ void CR(float v[24], int lane, int lm) {
    bool kp = (lane & lm) == 0;
#pragma unroll
    for (int r = 0; r < 24; r++) {
        float o = __shfl_xor_sync(FULLM, v[r], lm);
        v[r] = kp ? fminf(v[r], o) : fmaxf(v[r], o);
    }
}
// flip substage k=16..128: partner reg = r^7 (same octet), partner lane ^lmc.
// Processed per octet: <=8 temps live, reads always pre-update (octets disjoint).
__device__ __forceinline__ void FL(float v[24], int lane, int lmc, int pb) {
    bool kp = (lane & pb) == 0;
#pragma unroll
    for (int oct = 0; oct < 24; oct += 8) {
        float t[8];
#pragma unroll
        for (int i = 0; i < 8; i++) t[i] = __shfl_xor_sync(FULLM, v[oct + (i ^ 7)], lmc);
#pragma unroll
        for (int i = 0; i < 8; i++) v[oct + i] = kp ? fminf(v[oct + i], t[i])
                                                    : fmaxf(v[oct + i], t[i]);
    }
}
// flip k=256: pairs (r, 15-r), lane^15; hi2=2 partners virtual (pruned).
__device__ __forceinline__ void F256(float v[24]) {
#pragma unroll
    for (int h = 0; h < 2; h++) {
        int base = h ? 4 : 0;
        float t1[4], t2[4];
#pragma unroll
        for (int i = 0; i < 4; i++) {
            t1[i] = __shfl_xor_sync(FULLM, v[15 - (base + i)], 15);
            t2[i] = __shfl_xor_sync(FULLM, v[base + i], 15);
        }
#pragma unroll
        for (int i = 0; i < 4; i++) {
            v[base + i]        = fminf(v[base + i], t1[i]);
            v[15 - (base + i)] = fmaxf(v[15 - (base + i)], t2[i]);
        }
    }
}
// flip k=512: pairs (r, 31-r) for r=8..15, lane^15; r=0..7 partners virtual.
__device__ __forceinline__ void F512(float v[24]) {
#pragma unroll
    for (int h = 0; h < 2; h++) {
        int base = h ? 12 : 8;
        float t1[4], t2[4];
#pragma unroll
        for (int i = 0; i < 4; i++) {
            t1[i] = __shfl_xor_sync(FULLM, v[31 - (base + i)], 15);
            t2[i] = __shfl_xor_sync(FULLM, v[base + i], 15);
        }
#pragma unroll
        for (int i = 0; i < 4; i++) {
            v[base + i]        = fminf(v[base + i], t1[i]);
            v[31 - (base + i)] = fmaxf(v[31 - (base + i)], t2[i]);
        }
    }
}

__device__ __forceinline__ void bsort384h(float v[24], int lane) {
    P1(v);                                                   // k=2
    F3(v); P1(v);                                            // k=4
    F7(v); P2(v); P1(v);                                     // k=8
    FL(v, lane, 1, 1);  P4(v); P2(v); P1(v);                 // k=16
    FL(v, lane, 3, 2);  CR(v, lane, 1); P4(v); P2(v); P1(v); // k=32
    FL(v, lane, 7, 4);  CR(v, lane, 2); CR(v, lane, 1);
    P4(v); P2(v); P1(v);                                     // k=64
    FL(v, lane, 15, 8); CR(v, lane, 4); CR(v, lane, 2); CR(v, lane, 1);
    P4(v); P2(v); P1(v);                                     // k=128
    F256(v); CR(v, lane, 8); CR(v, lane, 4); CR(v, lane, 2); CR(v, lane, 1);
    P4(v); P2(v); P1(v);                                     // k=256
    F512(v); P128(v); CR(v, lane, 8); CR(v, lane, 4); CR(v, lane, 2);
    CR(v, lane, 1); P4(v); P2(v); P1(v);                     // k=512
}

// ================= full 512 sorter (lane-major, for k_theil) =================
__device__ __forceinline__ void bsort512(float v[16], int lane) {
#pragma unroll
    for (int k = 2; k <= 16; k <<= 1) {
#pragma unroll
        for (int r = 0; r < 16; r++)
            if ((r & (k - 1)) < (k >> 1)) cswapF(v[r], v[r ^ (k - 1)]);
#pragma unroll
        for (int j = 8; j >= 1; j >>= 1)
            if (j <= (k >> 2)) {
#pragma unroll
                for (int r = 0; r < 16; r++)
                    if ((r & j) == 0) cswapF(v[r], v[r | j]);
            }
    }
#pragma unroll
    for (int k = 32; k <= 512; k <<= 1) {
        {
            int  lm      = (k - 1) >> 4;
            bool keepmin = ((lane & (k >> 5)) == 0);
#pragma unroll
            for (int r = 0; r < 8; r++) {
                float a = __shfl_xor_sync(FULLM, v[15 - r], lm);
                float b = __shfl_xor_sync(FULLM, v[r], lm);
                v[r]      = keepmin ? fminf(v[r], a)      : fmaxf(v[r], a);
                v[15 - r] = keepmin ? fminf(v[15 - r], b) : fmaxf(v[15 - r], b);
            }
        }
#pragma unroll
        for (int j = 128; j >= 16; j >>= 1)
            if (j <= (k >> 2)) {
                int  lm      = j >> 4;
                bool keepmin = ((lane & lm) == 0);
#pragma unroll
                for (int r = 0; r < 16; r++) {
                    float o = __shfl_xor_sync(FULLM, v[r], lm);
                    v[r] = keepmin ? fminf(v[r], o) : fmaxf(v[r], o);
                }
            }
#pragma unroll
        for (int j = 8; j >= 1; j >>= 1) {
#pragma unroll
            for (int r = 0; r < 16; r++)
                if ((r & j) == 0) cswapF(v[r], v[r | j]);
        }
    }
}

// ---------------- kernel 0: zero accumulators + build pair tables ------------
__global__ void k_zero() {
    int tid = threadIdx.x;
    if (tid == 0) { g_sse = 0.0; g_trend = 0.0; }
    if (tid < NPAIR) {
        int i = 0, rem = tid, cnt = NY - 1;
        while (rem >= cnt) { rem -= cnt; i++; cnt--; }
        int j = i + 1 + rem;
        g_pairIJ[tid]  = i | (j << 8);
        g_pairInv[tid] = 1.0f / (float)(j - i);
    }
}

// ---------------- kernel 1: transpose + SSE + per-(series,year) sort ---------
// grid (SGRID/16, NY), block 256 (8 warps; each warp sorts 2 series per pass)
// __launch_bounds__(256, 4): pin regs <= 64 so smem-allowed 4 blocks/SM holds.
__global__ __launch_bounds__(256, 4) void k_sortdays(const float* __restrict__ pred,
                                                     const float* __restrict__ obs) {
    __shared__ float shP[K1_SER][SROW];
    __shared__ float shT[K1_SER][SROW];
    __shared__ float warpsum[8];

    int y      = blockIdx.y;
    int s_base = blockIdx.x * K1_SER;
    int tid    = threadIdx.x;
    int w      = tid >> 5;
    int lane   = tid & 31;
    int lane4  = lane & 15;

    const float* pbase = pred + (size_t)y * DAYS * SGRID + s_base;
    const float* tbase = obs  + (size_t)y * DAYS * SGRID + s_base;

    // coalesced load + transpose (day d -> addr (d&7)*46 + (d>>3)) + fused SSE
    float sse = 0.0f;
    for (int idx = tid; idx < DAYS * K1_SER; idx += 256) {
        int d  = idx >> 4;
        int sl = idx & 15;
        int ad = (d & 7) * 46 + (d >> 3);
        float a = pbase[d * SGRID + sl];
        float b = tbase[d * SGRID + sl];
        shP[sl][ad] = a;
        shT[sl][ad] = b;
        float df = a - b;
        sse += df * df;
    }
#pragma unroll
    for (int o = 16; o > 0; o >>= 1) sse += __shfl_down_sync(FULLM, sse, o);
    if (lane == 0) warpsum[w] = sse;
    __syncthreads();
    if (tid == 0) {
        float tot = 0.0f;
#pragma unroll
        for (int i = 0; i < 8; i++) tot += warpsum[i];
        atomicAdd(&g_sse, (double)tot);
    }

    // this half-warp's series
    int sidx = 2 * w + (lane >> 4);     // 0..15 within block
    int s    = s_base + sidx;

#pragma unroll 1
    for (int pass = 0; pass < 2; pass++) {
        const float* row = pass ? &shT[sidx][0] : &shP[sidx][0];
        float* outM = pass ? g_tM : g_pM;
        float* outQ = pass ? g_tQ : g_pQ;

        // load: reg r holds slot g = (r&7) | (lane4<<3) | ((r>>3)<<7)
        float v[24];
        float msum = 0.0f;
#pragma unroll
        for (int r = 0; r < 24; r++) {
            int lo3 = r & 7, hi2 = r >> 3;
            int g   = lo3 | (lane4 << 3) | (hi2 << 7);
            if (g < DAYS) { v[r] = row[lo3 * 46 + lane4 + (hi2 << 4)]; msum += v[r]; }
            else          { v[r] = POSINF; }
        }
        // per-half mean (xor butterfly within 16-lane half)
#pragma unroll
        for (int o = 8; o > 0; o >>= 1) msum += __shfl_xor_sync(FULLM, msum, o);
        if (lane4 == 0) outM[s * NY + y] = msum * (1.0f / (float)DAYS);

        bsort384h(v, lane);

        // rank R -> reg (R&7)|((R>>7)<<3), lane4 (R>>3)&15
        if (lane4 == 13) {
            outQ[(s * NQ + 0) * NY + y] = v[20];  // rank 364
            outQ[(s * NQ + 3) * NY + y] = v[5];   // rank 109
        }
        if (lane4 == 12) outQ[(s * NQ + 1) * NY + y] = v[21];  // rank 357
        if (lane4 == 6)  outQ[(s * NQ + 2) * NY + y] = v[14];  // rank 182
        if (lane4 == 0)  outQ[(s * NQ + 4) * NY + y] = v[7];   // rank 7
    }
}

// ---------------- kernel 2: Theil-Sen medians + trend terms ------------------
// grid SGRID, block 192 (6 warps: warp0 = mean, warps 1..5 = quantiles)
__global__ __launch_bounds__(192, 5) void k_theil() {
    __shared__ float xs[6][2][NY];

    int s    = blockIdx.x;
    int w    = threadIdx.x >> 5;
    int lane = threadIdx.x & 31;

    const float* xp;
    const float* xt;
    if (w == 0) { xp = g_pM + s * NY;                  xt = g_tM + s * NY; }
    else        { xp = g_pQ + (s * NQ + (w - 1)) * NY; xt = g_tQ + (s * NQ + (w - 1)) * NY; }
    if (lane < NY) {
        xs[w][0][lane] = xp[lane];
        xs[w][1][lane] = xt[lane];
    }
    __syncwarp();

    float med[2];
#pragma unroll 1
    for (int pass = 0; pass < 2; pass++) {
        float v[16];
#pragma unroll
        for (int r = 0; r < 16; r++) {
            int p = (r << 5) | lane;   // arbitrary pair->slot map (median is set-invariant)
            if (p < NPAIR) {
                int   ij  = g_pairIJ[p];
                float inv = g_pairInv[p];
                int i = ij & 255, j = ij >> 8;
                v[r] = (xs[w][pass][j] - xs[w][pass][i]) * inv;
            } else {
                v[r] = POSINF;
            }
        }
        bsort512(v, lane);
        // median of 435 = sorted element 217 -> lane 13, reg 9 (lane-major)
        med[pass] = __shfl_sync(FULLM, v[9], 13);
    }

    if (lane == 0) {
        float sp = med[0], st = med[1];
        double term;
        if (w == 0) { float d = st - sp;   term = (double)d * (double)d; }
        else        { float q = st / (-sp); term = (double)q * (double)q; }
        atomicAdd(&g_trend, term);
    }
}

// ---------------- kernel 3: finalize -----------------------------------------
__global__ void k_final(float* out) {
    double mse = g_sse / ((double)TT * (double)SGRID);
    out[0] = (float)(sqrt(mse) + g_trend / (double)SGRID);
}

// ---------------- launch ------------------------------------------------------
extern "C" void kernel_launch(void* const* d_in, const int* in_sizes, int n_in,
                              void* d_out, int out_size) {
    const float* y_pred = (const float*)d_in[0];
    const float* y_obs  = (const float*)d_in[1];
    float* out = (float*)d_out;

    k_zero<<<1, 512>>>();
    k_sortdays<<<dim3(SGRID / K1_SER, NY), 256>>>(y_pred, y_obs);
    k_theil<<<SGRID, 192>>>();
    k_final<<<1, 1>>>(out);
}

// round 11
// speedup vs baseline: 1.1027x; 1.0469x over previous
#include <cuda_runtime.h>
#include <math.h>

#define DAYS  365
#define NY    30
#define SGRID 4000
#define TT    (DAYS * NY)
#define NPAIR 435
#define NQ    5
#define K1_SER 16
#define SROW  369            // smem row stride (floats); row needs 368

#define POSINF __int_as_float(0x7f800000)
#define FULLM  0xffffffffu

// ---------------- intermediate storage (no allocations allowed) -------------
__device__ float  g_pM[SGRID * NY];
__device__ float  g_tM[SGRID * NY];
__device__ float  g_pQ[SGRID * NQ * NY];
__device__ float  g_tQ[SGRID * NQ * NY];
__device__ double g_sse;
__device__ double g_trend;
__device__ int    g_pairIJ[NPAIR];   // i | (j<<8)
__device__ float  g_pairInv[NPAIR];  // 1/(j-i)

// compile-time-direction comparator: a <- min, b <- max (2 FMNMX)
__device__ __forceinline__ void cswapF(float& a, float& b) {
    float lo = fminf(a, b), hi = fmaxf(a, b); a = lo; b = hi;
}

// Batcher odd-even merge sort of 8 (19 comparators, ascending) — replaces the
// bitonic k=2..8 levels (24 comparators) at the start of the 384 network.
__device__ __forceinline__ void sort8(float* v) {
    cswapF(v[0],v[1]); cswapF(v[2],v[3]); cswapF(v[0],v[2]); cswapF(v[1],v[3]);
    cswapF(v[1],v[2]);
    cswapF(v[4],v[5]); cswapF(v[6],v[7]); cswapF(v[4],v[6]); cswapF(v[5],v[7]);
    cswapF(v[5],v[6]);
    cswapF(v[0],v[4]); cswapF(v[1],v[5]); cswapF(v[2],v[6]); cswapF(v[3],v[7]);
    cswapF(v[2],v[4]); cswapF(v[3],v[5]);
    cswapF(v[1],v[2]); cswapF(v[3],v[4]); cswapF(v[5],v[6]);
}

// ============ 384-slot pruned bitonic, 24 regs, TWO series per warp ==========
// Slot g (9 bits): {g0,g1,g2} -> reg lo3, {g3..g6} -> lane4 (lane&15),
// {g7,g8} -> reg hi2 (hi2==3 virtual/pruned). r = lo3 | (hi2<<3), 0..23.
// lane bit 4 selects which of the two series this half-warp sorts.

__device__ __forceinline__ void P1(float v[24]) {
#pragma unroll
    for (int r = 0; r < 24; r++) if ((r & 1) == 0) cswapF(v[r], v[r | 1]);
}
__device__ __forceinline__ void P2(float v[24]) {
#pragma unroll
    for (int r = 0; r < 24; r++) if ((r & 2) == 0) cswapF(v[r], v[r | 2]);
}
__device__ __forceinline__ void P4(float v[24]) {
#pragma unroll
    for (int r = 0; r < 24; r++) if ((r & 4) == 0) cswapF(v[r], v[r | 4]);
}
__device__ __forceinline__ void P128(float v[24]) {   // hi2 0<->1; 2<->3 pruned
#pragma unroll
    for (int r = 0; r < 8; r++) cswapF(v[r], v[r + 8]);
}
// plain cross-lane substage: global stride 8*lm, lm in {1,2,4,8}
__device__ __forceinline__ void CR(float v[24], int lane, int lm) {
    bool kp = (lane & lm) == 0;
#pragma unroll
    for (int r = 0; r < 24; r++) {
        float o = __shfl_xor_sync(FULLM, v[r], lm);
        v[r] = kp ? fminf(v[r], o) : fmaxf(v[r], o);
    }
}
// flip substage k=16..128: partner reg = r^7 (same octet), partner lane ^lmc.
__device__ __forceinline__ void FL(float v[24], int lane, int lmc, int pb) {
    bool kp = (lane & pb) == 0;
#pragma unroll
    for (int oct = 0; oct < 24; oct += 8) {
        float t[8];
#pragma unroll
        for (int i = 0; i < 8; i++) t[i] = __shfl_xor_sync(FULLM, v[oct + (i ^ 7)], lmc);
#pragma unroll
        for (int i = 0; i < 8; i++) v[oct + i] = kp ? fminf(v[oct + i], t[i])
                                                    : fmaxf(v[oct + i], t[i]);
    }
}
// flip k=256: pairs (r, 15-r), lane^15; hi2=2 partners virtual (pruned).
__device__ __forceinline__ void F256(float v[24]) {
#pragma unroll
    for (int h = 0; h < 2; h++) {
        int base = h ? 4 : 0;
        float t1[4], t2[4];
#pragma unroll
        for (int i = 0; i < 4; i++) {
            t1[i] = __shfl_xor_sync(FULLM, v[15 - (base + i)], 15);
            t2[i] = __shfl_xor_sync(FULLM, v[base + i], 15);
        }
#pragma unroll
        for (int i = 0; i < 4; i++) {
            v[base + i]        = fminf(v[base + i], t1[i]);
            v[15 - (base + i)] = fmaxf(v[15 - (base + i)], t2[i]);
        }
    }
}
// flip k=512: pairs (r, 31-r) for r=8..15, lane^15; r=0..7 partners virtual.
__device__ __forceinline__ void F512(float v[24]) {
#pragma unroll
    for (int h = 0; h < 2; h++) {
        int base = h ? 12 : 8;
        float t1[4], t2[4];
#pragma unroll
        for (int i = 0; i < 4; i++) {
            t1[i] = __shfl_xor_sync(FULLM, v[31 - (base + i)], 15);
            t2[i] = __shfl_xor_sync(FULLM, v[base + i], 15);
        }
#pragma unroll
        for (int i = 0; i < 4; i++) {
            v[base + i]        = fminf(v[base + i], t1[i]);
            v[31 - (base + i)] = fmaxf(v[31 - (base + i)], t2[i]);
        }
    }
}

__device__ __forceinline__ void bsort384h(float v[24], int lane) {
    sort8(v); sort8(v + 8); sort8(v + 16);                   // k<=8 (OEM-8 x3)
    FL(v, lane, 1, 1);  P4(v); P2(v); P1(v);                 // k=16
    FL(v, lane, 3, 2);  CR(v, lane, 1); P4(v); P2(v); P1(v); // k=32
    FL(v, lane, 7, 4);  CR(v, lane, 2); CR(v, lane, 1);
    P4(v); P2(v); P1(v);                                     // k=64
    FL(v, lane, 15, 8); CR(v, lane, 4); CR(v, lane, 2); CR(v, lane, 1);
    P4(v); P2(v); P1(v);                                     // k=128
    F256(v); CR(v, lane, 8); CR(v, lane, 4); CR(v, lane, 2); CR(v, lane, 1);
    P4(v); P2(v); P1(v);                                     // k=256
    F512(v); P128(v); CR(v, lane, 8); CR(v, lane, 4); CR(v, lane, 2);
    CR(v, lane, 1); P4(v); P2(v); P1(v);                     // k=512
}

// ================= full 512 sorter (lane-major, for k_theil) =================
__device__ __forceinline__ void bsort512(float v[16], int lane) {
#pragma unroll
    for (int k = 2; k <= 16; k <<= 1) {
#pragma unroll
        for (int r = 0; r < 16; r++)
            if ((r & (k - 1)) < (k >> 1)) cswapF(v[r], v[r ^ (k - 1)]);
#pragma unroll
        for (int j = 8; j >= 1; j >>= 1)
            if (j <= (k >> 2)) {
#pragma unroll
                for (int r = 0; r < 16; r++)
                    if ((r & j) == 0) cswapF(v[r], v[r | j]);
            }
    }
#pragma unroll
    for (int k = 32; k <= 512; k <<= 1) {
        {
            int  lm      = (k - 1) >> 4;
            bool keepmin = ((lane & (k >> 5)) == 0);
#pragma unroll
            for (int r = 0; r < 8; r++) {
                float a = __shfl_xor_sync(FULLM, v[15 - r], lm);
                float b = __shfl_xor_sync(FULLM, v[r], lm);
                v[r]      = keepmin ? fminf(v[r], a)      : fmaxf(v[r], a);
                v[15 - r] = keepmin ? fminf(v[15 - r], b) : fmaxf(v[15 - r], b);
            }
        }
#pragma unroll
        for (int j = 128; j >= 16; j >>= 1)
            if (j <= (k >> 2)) {
                int  lm      = j >> 4;
                bool keepmin = ((lane & lm) == 0);
#pragma unroll
                for (int r = 0; r < 16; r++) {
                    float o = __shfl_xor_sync(FULLM, v[r], lm);
                    v[r] = keepmin ? fminf(v[r], o) : fmaxf(v[r], o);
                }
            }
#pragma unroll
        for (int j = 8; j >= 1; j >>= 1) {
#pragma unroll
            for (int r = 0; r < 16; r++)
                if ((r & j) == 0) cswapF(v[r], v[r | j]);
        }
    }
}

// ---------------- kernel 0: zero accumulators + build pair tables ------------
__global__ void k_zero() {
    int tid = threadIdx.x;
    if (tid == 0) { g_sse = 0.0; g_trend = 0.0; }
    if (tid < NPAIR) {
        int i = 0, rem = tid, cnt = NY - 1;
        while (rem >= cnt) { rem -= cnt; i++; cnt--; }
        int j = i + 1 + rem;
        g_pairIJ[tid]  = i | (j << 8);
        g_pairInv[tid] = 1.0f / (float)(j - i);
    }
}

// ---------------- kernel 1: transpose + SSE + per-(series,year) sort ---------
// grid (SGRID/16, NY), block 256 (8 warps; each warp sorts 2 series per pass)
__global__ __launch_bounds__(256, 4) void k_sortdays(const float* __restrict__ pred,
                                                     const float* __restrict__ obs) {
    __shared__ float shP[K1_SER][SROW];
    __shared__ float shT[K1_SER][SROW];
    __shared__ float warpsum[8];

    int y      = blockIdx.y;
    int s_base = blockIdx.x * K1_SER;
    int tid    = threadIdx.x;
    int w      = tid >> 5;
    int lane   = tid & 31;
    int lane4  = lane & 31 & 15;

    const float* pbase = pred + (size_t)y * DAYS * SGRID + s_base;
    const float* tbase = obs  + (size_t)y * DAYS * SGRID + s_base;

    // vectorized coalesced load + transpose (day d -> col (d&7)*46+(d>>3)) + SSE
    float sse = 0.0f;
    for (int idx = tid; idx < DAYS * 4; idx += 256) {
        int d  = idx >> 2;
        int q  = (idx & 3) << 2;
        int ad = (d & 7) * 46 + (d >> 3);
        float4 a4 = *(const float4*)(pbase + d * SGRID + q);
        float4 b4 = *(const float4*)(tbase + d * SGRID + q);
        shP[q + 0][ad] = a4.x;  shT[q + 0][ad] = b4.x;
        shP[q + 1][ad] = a4.y;  shT[q + 1][ad] = b4.y;
        shP[q + 2][ad] = a4.z;  shT[q + 2][ad] = b4.z;
        shP[q + 3][ad] = a4.w;  shT[q + 3][ad] = b4.w;
        float dx = a4.x - b4.x, dy = a4.y - b4.y;
        float dz = a4.z - b4.z, dw = a4.w - b4.w;
        sse += dx * dx + dy * dy + dz * dz + dw * dw;
    }
#pragma unroll
    for (int o = 16; o > 0; o >>= 1) sse += __shfl_down_sync(FULLM, sse, o);
    if (lane == 0) warpsum[w] = sse;
    __syncthreads();
    if (tid == 0) {
        float tot = 0.0f;
#pragma unroll
        for (int i = 0; i < 8; i++) tot += warpsum[i];
        atomicAdd(&g_sse, (double)tot);
    }

    // this half-warp's series
    int sidx = 2 * w + (lane >> 4);     // 0..15 within block
    int s    = s_base + sidx;

#pragma unroll 1
    for (int pass = 0; pass < 2; pass++) {
        const float* row = pass ? &shT[sidx][0] : &shP[sidx][0];
        float* outM = pass ? g_tM : g_pM;
        float* outQ = pass ? g_tQ : g_pQ;

        // load: reg r holds slot g = (r&7) | (lane4<<3) | ((r>>3)<<7)
        float v[24];
        float msum = 0.0f;
#pragma unroll
        for (int r = 0; r < 24; r++) {
            int lo3 = r & 7, hi2 = r >> 3;
            int g   = lo3 | (lane4 << 3) | (hi2 << 7);
            if (g < DAYS) { v[r] = row[lo3 * 46 + lane4 + (hi2 << 4)]; msum += v[r]; }
            else          { v[r] = POSINF; }
        }
        // per-half mean (xor butterfly within 16-lane half)
#pragma unroll
        for (int o = 8; o > 0; o >>= 1) msum += __shfl_xor_sync(FULLM, msum, o);
        if (lane4 == 0) outM[s * NY + y] = msum * (1.0f / (float)DAYS);

        bsort384h(v, lane);

        // rank R -> reg (R&7)|((R>>7)<<3), lane4 (R>>3)&15
        if (lane4 == 13) {
            outQ[(s * NQ + 0) * NY + y] = v[20];  // rank 364
            outQ[(s * NQ + 3) * NY + y] = v[5];   // rank 109
        }
        if (lane4 == 12) outQ[(s * NQ + 1) * NY + y] = v[21];  // rank 357
        if (lane4 == 6)  outQ[(s * NQ + 2) * NY + y] = v[14];  // rank 182
        if (lane4 == 0)  outQ[(s * NQ + 4) * NY + y] = v[7];   // rank 7
    }
}

// ---------------- kernel 2: Theil-Sen medians + trend terms ------------------
// grid SGRID, block 192 (6 warps: warp0 = mean, warps 1..5 = quantiles)
// Both sorts (P and T) run in one straight-line region for 2x ILP.
__global__ __launch_bounds__(192, 5) void k_theil() {
    __shared__ float xs[6][2][NY];

    int s    = blockIdx.x;
    int w    = threadIdx.x >> 5;
    int lane = threadIdx.x & 31;

    const float* xp;
    const float* xt;
    if (w == 0) { xp = g_pM + s * NY;                  xt = g_tM + s * NY; }
    else        { xp = g_pQ + (s * NQ + (w - 1)) * NY; xt = g_tQ + (s * NQ + (w - 1)) * NY; }
    if (lane < NY) {
        xs[w][0][lane] = xp[lane];
        xs[w][1][lane] = xt[lane];
    }
    __syncwarp();

    float vP[16], vT[16];
#pragma unroll
    for (int r = 0; r < 16; r++) {
        int p = (r << 5) | lane;   // arbitrary pair->slot map (median is set-invariant)
        if (p < NPAIR) {
            int   ij  = g_pairIJ[p];
            float inv = g_pairInv[p];
            int i = ij & 255, j = ij >> 8;
            vP[r] = (xs[w][0][j] - xs[w][0][i]) * inv;
            vT[r] = (xs[w][1][j] - xs[w][1][i]) * inv;
        } else {
            vP[r] = POSINF;
            vT[r] = POSINF;
        }
    }

    bsort512(vP, lane);
    bsort512(vT, lane);

    // median of 435 = sorted element 217 -> lane 13, reg 9 (lane-major)
    float sp = __shfl_sync(FULLM, vP[9], 13);
    float st = __shfl_sync(FULLM, vT[9], 13);

    if (lane == 0) {
        double term;
        if (w == 0) { float d = st - sp;   term = (double)d * (double)d; }
        else        { float q = st / (-sp); term = (double)q * (double)q; }
        atomicAdd(&g_trend, term);
    }
}

// ---------------- kernel 3: finalize -----------------------------------------
__global__ void k_final(float* out) {
    double mse = g_sse / ((double)TT * (double)SGRID);
    out[0] = (float)(sqrt(mse) + g_trend / (double)SGRID);
}

// ---------------- launch ------------------------------------------------------
extern "C" void kernel_launch(void* const* d_in, const int* in_sizes, int n_in,
                              void* d_out, int out_size) {
    const float* y_pred = (const float*)d_in[0];
    const float* y_obs  = (const float*)d_in[1];
    float* out = (float*)d_out;

    k_zero<<<1, 512>>>();
    k_sortdays<<<dim3(SGRID / K1_SER, NY), 256>>>(y_pred, y_obs);
    k_theil<<<SGRID, 192>>>();
    k_final<<<1, 1>>>(out);
}

// round 12
// speedup vs baseline: 1.2430x; 1.1272x over previous
#include <cuda_runtime.h>
#include <math.h>

#define DAYS  365
#define NY    30
#define SGRID 4000
#define TT    (DAYS * NY)
#define NPAIR 435
#define NQ    5
#define K1_SER 16
#define SROW  397            // row stride; layout needs 368, sorted scratch 395

#define POSINF __int_as_float(0x7f800000)
#define NEGINF __int_as_float(0xff800000)
#define FULLM  0xffffffffu

// ---------------- intermediate storage (no allocations allowed) -------------
__device__ float  g_pM[SGRID * NY];
__device__ float  g_tM[SGRID * NY];
__device__ float  g_pQ[SGRID * NQ * NY];
__device__ float  g_tQ[SGRID * NQ * NY];
__device__ double g_sse;
__device__ double g_trend;
__device__ int    g_pairIJ[NPAIR];   // i | (j<<8)
__device__ float  g_pairInv[NPAIR];  // 1/(j-i)

// compile-time-direction comparator: a <- min, b <- max (2 FMNMX)
__device__ __forceinline__ void cswapF(float& a, float& b) {
    float lo = fminf(a, b), hi = fmaxf(a, b); a = lo; b = hi;
}

// Batcher odd-even merge sort of 8 (19 comparators, ascending)
__device__ __forceinline__ void sort8(float* v) {
    cswapF(v[0],v[1]); cswapF(v[2],v[3]); cswapF(v[0],v[2]); cswapF(v[1],v[3]);
    cswapF(v[1],v[2]);
    cswapF(v[4],v[5]); cswapF(v[6],v[7]); cswapF(v[4],v[6]); cswapF(v[5],v[7]);
    cswapF(v[5],v[6]);
    cswapF(v[0],v[4]); cswapF(v[1],v[5]); cswapF(v[2],v[6]); cswapF(v[3],v[7]);
    cswapF(v[2],v[4]); cswapF(v[3],v[5]);
    cswapF(v[1],v[2]); cswapF(v[3],v[4]); cswapF(v[5],v[6]);
}

// ============ pruned bitonic through k=256, 24 regs, TWO series/warp =========
// Slot g: {g0,g1,g2}->reg lo3, {g3..g6}->lane4, {g7,g8}->reg hi2 (hi2=3 virtual).
// After this, slots 0..255 (r0..15) ascending and 256..383 (r16..23) ascending.

__device__ __forceinline__ void P1(float v[24]) {
#pragma unroll
    for (int r = 0; r < 24; r++) if ((r & 1) == 0) cswapF(v[r], v[r | 1]);
}
__device__ __forceinline__ void P2(float v[24]) {
#pragma unroll
    for (int r = 0; r < 24; r++) if ((r & 2) == 0) cswapF(v[r], v[r | 2]);
}
__device__ __forceinline__ void P4(float v[24]) {
#pragma unroll
    for (int r = 0; r < 24; r++) if ((r & 4) == 0) cswapF(v[r], v[r | 4]);
}
// r<16 variants for the k=256 level (block1 r16..23 already sorted there)
__device__ __forceinline__ void P1h(float v[24]) {
#pragma unroll
    for (int r = 0; r < 16; r++) if ((r & 1) == 0) cswapF(v[r], v[r | 1]);
}
__device__ __forceinline__ void P2h(float v[24]) {
#pragma unroll
    for (int r = 0; r < 16; r++) if ((r & 2) == 0) cswapF(v[r], v[r | 2]);
}
__device__ __forceinline__ void P4h(float v[24]) {
#pragma unroll
    for (int r = 0; r < 16; r++) if ((r & 4) == 0) cswapF(v[r], v[r | 4]);
}
__device__ __forceinline__ void CR(float v[24], int lane, int lm) {
    bool kp = (lane & lm) == 0;
#pragma unroll
    for (int r = 0; r < 24; r++) {
        float o = __shfl_xor_sync(FULLM, v[r], lm);
        v[r] = kp ? fminf(v[r], o) : fmaxf(v[r], o);
    }
}
__device__ __forceinline__ void CRh(float v[24], int lane, int lm) {
    bool kp = (lane & lm) == 0;
#pragma unroll
    for (int r = 0; r < 16; r++) {
        float o = __shfl_xor_sync(FULLM, v[r], lm);
        v[r] = kp ? fminf(v[r], o) : fmaxf(v[r], o);
    }
}
__device__ __forceinline__ void FL(float v[24], int lane, int lmc, int pb) {
    bool kp = (lane & pb) == 0;
#pragma unroll
    for (int oct = 0; oct < 24; oct += 8) {
        float t[8];
#pragma unroll
        for (int i = 0; i < 8; i++) t[i] = __shfl_xor_sync(FULLM, v[oct + (i ^ 7)], lmc);
#pragma unroll
        for (int i = 0; i < 8; i++) v[oct + i] = kp ? fminf(v[oct + i], t[i])
                                                    : fmaxf(v[oct + i], t[i]);
    }
}
__device__ __forceinline__ void F256(float v[24]) {
#pragma unroll
    for (int h = 0; h < 2; h++) {
        int base = h ? 4 : 0;
        float t1[4], t2[4];
#pragma unroll
        for (int i = 0; i < 4; i++) {
            t1[i] = __shfl_xor_sync(FULLM, v[15 - (base + i)], 15);
            t2[i] = __shfl_xor_sync(FULLM, v[base + i], 15);
        }
#pragma unroll
        for (int i = 0; i < 4; i++) {
            v[base + i]        = fminf(v[base + i], t1[i]);
            v[15 - (base + i)] = fmaxf(v[15 - (base + i)], t2[i]);
        }
    }
}

__device__ __forceinline__ void bsort2runs(float v[24], int lane) {
    sort8(v); sort8(v + 8); sort8(v + 16);                   // k<=8
    FL(v, lane, 1, 1);  P4(v); P2(v); P1(v);                 // k=16
    FL(v, lane, 3, 2);  CR(v, lane, 1); P4(v); P2(v); P1(v); // k=32
    FL(v, lane, 7, 4);  CR(v, lane, 2); CR(v, lane, 1);
    P4(v); P2(v); P1(v);                                     // k=64
    FL(v, lane, 15, 8); CR(v, lane, 4); CR(v, lane, 2); CR(v, lane, 1);
    P4(v); P2(v); P1(v);                                     // k=128
    F256(v); CRh(v, lane, 8); CRh(v, lane, 4); CRh(v, lane, 2); CRh(v, lane, 1);
    P4h(v); P2h(v); P1h(v);                                  // k=256 (r<16)
}

// select rank k (1-based) from sorted A (m entries) + sorted B (n entries),
// both stored padded: element at slot g lives at base[g + (g>>5)], B at slot
// boff+g. 9 guarded bisection steps (covers interval <= 257).
__device__ __forceinline__ float kth2(const float* base, int boff, int m, int n, int k) {
    int lo = max(0, k - n), hi = min(k, m);
#pragma unroll
    for (int it = 0; it < 9; it++) {
        int i  = (lo + hi + 1) >> 1;
        int ia = max(i - 1, 0);
        float Av = base[ia + (ia >> 5)];
        int j = k - i;
        int gb = boff + j;
        float Bv = (j < n) ? base[gb + (gb >> 5)] : POSINF;
        if (lo < hi) { if (Av <= Bv) lo = i; else hi = i - 1; }
    }
    int i = lo, j = k - lo;
    int ia = i - 1, jb = j - 1;
    float av = NEGINF, bv = NEGINF;
    if (i > 0) av = base[ia + (ia >> 5)];
    if (j > 0 && jb < n) { int gb = boff + jb; bv = base[gb + (gb >> 5)]; }
    return fmaxf(av, bv);
}

// ============== bitonic through k=256, lane-major (k_theil) ==================
__device__ __forceinline__ void bsort2runs512(float v[16], int lane) {
#pragma unroll
    for (int k = 2; k <= 16; k <<= 1) {
#pragma unroll
        for (int r = 0; r < 16; r++)
            if ((r & (k - 1)) < (k >> 1)) cswapF(v[r], v[r ^ (k - 1)]);
#pragma unroll
        for (int j = 8; j >= 1; j >>= 1)
            if (j <= (k >> 2)) {
#pragma unroll
                for (int r = 0; r < 16; r++)
                    if ((r & j) == 0) cswapF(v[r], v[r | j]);
            }
    }
#pragma unroll
    for (int k = 32; k <= 256; k <<= 1) {
        {
            int  lm      = (k - 1) >> 4;
            bool keepmin = ((lane & (k >> 5)) == 0);
#pragma unroll
            for (int r = 0; r < 8; r++) {
                float a = __shfl_xor_sync(FULLM, v[15 - r], lm);
                float b = __shfl_xor_sync(FULLM, v[r], lm);
                v[r]      = keepmin ? fminf(v[r], a)      : fmaxf(v[r], a);
                v[15 - r] = keepmin ? fminf(v[15 - r], b) : fmaxf(v[15 - r], b);
            }
        }
#pragma unroll
        for (int j = 128; j >= 16; j >>= 1)
            if (j <= (k >> 2)) {
                int  lm      = j >> 4;
                bool keepmin = ((lane & lm) == 0);
#pragma unroll
                for (int r = 0; r < 16; r++) {
                    float o = __shfl_xor_sync(FULLM, v[r], lm);
                    v[r] = keepmin ? fminf(v[r], o) : fmaxf(v[r], o);
                }
            }
#pragma unroll
        for (int j = 8; j >= 1; j >>= 1)
            if (j <= (k >> 2)) {
#pragma unroll
                for (int r = 0; r < 16; r++)
                    if ((r & j) == 0) cswapF(v[r], v[r | j]);
            }
    }
}

// ---------------- kernel 0: zero accumulators + build pair tables ------------
__global__ void k_zero() {
    int tid = threadIdx.x;
    if (tid == 0) { g_sse = 0.0; g_trend = 0.0; }
    if (tid < NPAIR) {
        int i = 0, rem = tid, cnt = NY - 1;
        while (rem >= cnt) { rem -= cnt; i++; cnt--; }
        int j = i + 1 + rem;
        g_pairIJ[tid]  = i | (j << 8);
        g_pairInv[tid] = 1.0f / (float)(j - i);
    }
}

// ---------------- kernel 1: transpose + SSE + sort-to-2-runs + select --------
// grid (SGRID/16, NY), block 256; dynamic smem 2*16*SROW*4 bytes.
__global__ __launch_bounds__(256, 4) void k_sortdays(const float* __restrict__ pred,
                                                     const float* __restrict__ obs) {
    extern __shared__ float dsm[];
    float* shP = dsm;                       // [16][SROW]
    float* shT = dsm + K1_SER * SROW;
    __shared__ float warpsum[8];

    int y      = blockIdx.y;
    int s_base = blockIdx.x * K1_SER;
    int tid    = threadIdx.x;
    int w      = tid >> 5;
    int lane   = tid & 31;
    int lane4  = lane & 15;

    const float* pbase = pred + (size_t)y * DAYS * SGRID + s_base;
    const float* tbase = obs  + (size_t)y * DAYS * SGRID + s_base;

    // vectorized coalesced load + transpose (day d -> col (d&7)*46+(d>>3)) + SSE
    float sse = 0.0f;
    for (int idx = tid; idx < DAYS * 4; idx += 256) {
        int d  = idx >> 2;
        int q  = (idx & 3) << 2;
        int ad = (d & 7) * 46 + (d >> 3);
        float4 a4 = *(const float4*)(pbase + d * SGRID + q);
        float4 b4 = *(const float4*)(tbase + d * SGRID + q);
        shP[(q + 0) * SROW + ad] = a4.x;  shT[(q + 0) * SROW + ad] = b4.x;
        shP[(q + 1) * SROW + ad] = a4.y;  shT[(q + 1) * SROW + ad] = b4.y;
        shP[(q + 2) * SROW + ad] = a4.z;  shT[(q + 2) * SROW + ad] = b4.z;
        shP[(q + 3) * SROW + ad] = a4.w;  shT[(q + 3) * SROW + ad] = b4.w;
        float dx = a4.x - b4.x, dy = a4.y - b4.y;
        float dz = a4.z - b4.z, dw = a4.w - b4.w;
        sse += dx * dx + dy * dy + dz * dz + dw * dw;
    }
#pragma unroll
    for (int o = 16; o > 0; o >>= 1) sse += __shfl_down_sync(FULLM, sse, o);
    if (lane == 0) warpsum[w] = sse;
    __syncthreads();
    if (tid == 0) {
        float tot = 0.0f;
#pragma unroll
        for (int i = 0; i < 8; i++) tot += warpsum[i];
        atomicAdd(&g_sse, (double)tot);
    }

    int sidx = 2 * w + (lane >> 4);     // this half-warp's series (0..15)
    int s    = s_base + sidx;

#pragma unroll 1
    for (int pass = 0; pass < 2; pass++) {
        float* row  = (pass ? shT : shP) + sidx * SROW;
        float* outM = pass ? g_tM : g_pM;
        float* outQ = pass ? g_tQ : g_pQ;

        // load: reg r holds slot g = (r&7) | (lane4<<3) | ((r>>3)<<7)
        float v[24];
        float msum = 0.0f;
#pragma unroll
        for (int r = 0; r < 24; r++) {
            int lo3 = r & 7, hi2 = r >> 3;
            int g   = lo3 | (lane4 << 3) | (hi2 << 7);
            if (g < DAYS) { v[r] = row[lo3 * 46 + lane4 + (hi2 << 4)]; msum += v[r]; }
            else          { v[r] = POSINF; }
        }
#pragma unroll
        for (int o = 8; o > 0; o >>= 1) msum += __shfl_xor_sync(FULLM, msum, o);
        if (lane4 == 0) outM[s * NY + y] = msum * (1.0f / (float)DAYS);

        bsort2runs(v, lane);

        // dump sorted runs: slot g -> row[g + (g>>5)]  (conflict-free padding)
#pragma unroll
        for (int r = 0; r < 24; r++) {
            int g = (r & 7) | (lane4 << 3) | ((r >> 3) << 7);
            row[g + (g >> 5)] = v[r];
        }
        __syncwarp();

        // lanes 0..4 of each half select one rank from A(256) + B(128)
        int R = lane4 == 0 ? 364 : lane4 == 1 ? 357 : lane4 == 2 ? 182
              : lane4 == 3 ? 109 : 7;
        float ans = kth2(row, 256, 256, 128, R + 1);
        if (lane4 < NQ) outQ[(s * NQ + lane4) * NY + y] = ans;
        __syncwarp();   // row reused as shT scratch region only after all reads
    }
}

// ---------------- kernel 2: Theil-Sen medians + trend terms ------------------
// grid SGRID, block 192 (6 warps: warp0 = mean, warps 1..5 = quantiles)
__global__ __launch_bounds__(192, 5) void k_theil() {
    __shared__ float xs[6][2][NY];
    __shared__ float scr[6][2][528];    // 512 slots + (g>>5) padding

    int s    = blockIdx.x;
    int w    = threadIdx.x >> 5;
    int lane = threadIdx.x & 31;

    const float* xp;
    const float* xt;
    if (w == 0) { xp = g_pM + s * NY;                  xt = g_tM + s * NY; }
    else        { xp = g_pQ + (s * NQ + (w - 1)) * NY; xt = g_tQ + (s * NQ + (w - 1)) * NY; }
    if (lane < NY) {
        xs[w][0][lane] = xp[lane];
        xs[w][1][lane] = xt[lane];
    }
    __syncwarp();

    float vP[16], vT[16];
#pragma unroll
    for (int r = 0; r < 16; r++) {
        int p = (r << 5) | lane;   // slot g = (lane<<4)|r gets pair p (arbitrary map)
        if (p < NPAIR) {
            int   ij  = g_pairIJ[p];
            float inv = g_pairInv[p];
            int i = ij & 255, j = ij >> 8;
            vP[r] = (xs[w][0][j] - xs[w][0][i]) * inv;
            vT[r] = (xs[w][1][j] - xs[w][1][i]) * inv;
        } else {
            vP[r] = POSINF;
            vT[r] = POSINF;
        }
    }

    bsort2runs512(vP, lane);   // two sorted 256-runs: slots 0..255 / 256..511
    bsort2runs512(vT, lane);

#pragma unroll
    for (int r = 0; r < 16; r++) {
        int g = (lane << 4) | r;
        int a = g + (g >> 5);
        scr[w][0][a] = vP[r];
        scr[w][1][a] = vT[r];
    }
    __syncwarp();

    // lane 0 selects median (rank 217, k=218) of P, lane 1 of T
    const float* base = (lane == 1) ? &scr[w][1][0] : &scr[w][0][0];
    float ans = kth2(base, 256, 256, 256, 218);
    float sp = __shfl_sync(FULLM, ans, 0);
    float st = __shfl_sync(FULLM, ans, 1);

    if (lane == 0) {
        double term;
        if (w == 0) { float d = st - sp;   term = (double)d * (double)d; }
        else        { float q = st / (-sp); term = (double)q * (double)q; }
        atomicAdd(&g_trend, term);
    }
}

// ---------------- kernel 3: finalize -----------------------------------------
__global__ void k_final(float* out) {
    double mse = g_sse / ((double)TT * (double)SGRID);
    out[0] = (float)(sqrt(mse) + g_trend / (double)SGRID);
}

// ---------------- launch ------------------------------------------------------
extern "C" void kernel_launch(void* const* d_in, const int* in_sizes, int n_in,
                              void* d_out, int out_size) {
    const float* y_pred = (const float*)d_in[0];
    const float* y_obs  = (const float*)d_in[1];
    float* out = (float*)d_out;

    const int dyn = 2 * K1_SER * SROW * (int)sizeof(float);  // 50,816 B
    cudaFuncSetAttribute(k_sortdays, cudaFuncAttributeMaxDynamicSharedMemorySize, dyn);

    k_zero<<<1, 512>>>();
    k_sortdays<<<dim3(SGRID / K1_SER, NY), 256, dyn>>>(y_pred, y_obs);
    k_theil<<<SGRID, 192>>>();
    k_final<<<1, 1>>>(out);
}

// round 13
// speedup vs baseline: 1.2451x; 1.0017x over previous
#include <cuda_runtime.h>
#include <math.h>

#define DAYS  365
#define NY    30
#define SGRID 4000
#define TT    (DAYS * NY)
#define NPAIR 435
#define NQ    5
#define K1_SER 16
#define SROW  397            // row stride; layout needs 368, sorted scratch 395

#define POSINF __int_as_float(0x7f800000)
#define NEGINF __int_as_float(0xff800000)
#define FULLM  0xffffffffu

// ---------------- intermediate storage (no allocations allowed) -------------
__device__ float  g_pM[SGRID * NY];
__device__ float  g_tM[SGRID * NY];
__device__ float  g_pQ[SGRID * NQ * NY];
__device__ float  g_tQ[SGRID * NQ * NY];
__device__ double g_sse;
__device__ double g_trend;
__device__ int    g_pairIJ[NPAIR];   // i | (j<<8)
__device__ float  g_pairInv[NPAIR];  // 1/(j-i)

__device__ __forceinline__ void cswapF(float& a, float& b) {
    float lo = fminf(a, b), hi = fmaxf(a, b); a = lo; b = hi;
}
// dual comparator: same network position applied to both streams
__device__ __forceinline__ void csw2(float& pa, float& pb, float& ta, float& tb) {
    cswapF(pa, pb); cswapF(ta, tb);
}

// Batcher odd-even merge sort of 8, dual-stream
__device__ __forceinline__ void sort8_2(float* p, float* t) {
    csw2(p[0],p[1],t[0],t[1]); csw2(p[2],p[3],t[2],t[3]);
    csw2(p[0],p[2],t[0],t[2]); csw2(p[1],p[3],t[1],t[3]);
    csw2(p[1],p[2],t[1],t[2]);
    csw2(p[4],p[5],t[4],t[5]); csw2(p[6],p[7],t[6],t[7]);
    csw2(p[4],p[6],t[4],t[6]); csw2(p[5],p[7],t[5],t[7]);
    csw2(p[5],p[6],t[5],t[6]);
    csw2(p[0],p[4],t[0],t[4]); csw2(p[1],p[5],t[1],t[5]);
    csw2(p[2],p[6],t[2],t[6]); csw2(p[3],p[7],t[3],t[7]);
    csw2(p[2],p[4],t[2],t[4]); csw2(p[3],p[5],t[3],t[5]);
    csw2(p[1],p[2],t[1],t[2]); csw2(p[3],p[4],t[3],t[4]);
    csw2(p[5],p[6],t[5],t[6]);
}

// ====== dual 384-slot pruned bitonic (to 2 sorted runs), 2 series/warp =======
// Slot g: {g0,g1,g2}->reg lo3, {g3..g6}->lane4, {g7,g8}->reg hi2 (hi2=3 virtual)

__device__ __forceinline__ void P1_2(float p[24], float t[24]) {
#pragma unroll
    for (int r = 0; r < 24; r++) if ((r & 1) == 0) csw2(p[r],p[r|1],t[r],t[r|1]);
}
__device__ __forceinline__ void P2_2(float p[24], float t[24]) {
#pragma unroll
    for (int r = 0; r < 24; r++) if ((r & 2) == 0) csw2(p[r],p[r|2],t[r],t[r|2]);
}
__device__ __forceinline__ void P4_2(float p[24], float t[24]) {
#pragma unroll
    for (int r = 0; r < 24; r++) if ((r & 4) == 0) csw2(p[r],p[r|4],t[r],t[r|4]);
}
__device__ __forceinline__ void P1h2(float p[24], float t[24]) {
#pragma unroll
    for (int r = 0; r < 16; r++) if ((r & 1) == 0) csw2(p[r],p[r|1],t[r],t[r|1]);
}
__device__ __forceinline__ void P2h2(float p[24], float t[24]) {
#pragma unroll
    for (int r = 0; r < 16; r++) if ((r & 2) == 0) csw2(p[r],p[r|2],t[r],t[r|2]);
}
__device__ __forceinline__ void P4h2(float p[24], float t[24]) {
#pragma unroll
    for (int r = 0; r < 16; r++) if ((r & 4) == 0) csw2(p[r],p[r|4],t[r],t[r|4]);
}
__device__ __forceinline__ void CR2(float p[24], float t[24], int lane, int lm) {
    bool kp = (lane & lm) == 0;
#pragma unroll
    for (int r = 0; r < 24; r++) {
        float oP = __shfl_xor_sync(FULLM, p[r], lm);
        float oT = __shfl_xor_sync(FULLM, t[r], lm);
        p[r] = kp ? fminf(p[r], oP) : fmaxf(p[r], oP);
        t[r] = kp ? fminf(t[r], oT) : fmaxf(t[r], oT);
    }
}
__device__ __forceinline__ void CRh2(float p[24], float t[24], int lane, int lm) {
    bool kp = (lane & lm) == 0;
#pragma unroll
    for (int r = 0; r < 16; r++) {
        float oP = __shfl_xor_sync(FULLM, p[r], lm);
        float oT = __shfl_xor_sync(FULLM, t[r], lm);
        p[r] = kp ? fminf(p[r], oP) : fmaxf(p[r], oP);
        t[r] = kp ? fminf(t[r], oT) : fmaxf(t[r], oT);
    }
}
__device__ __forceinline__ void FL2(float p[24], float t[24], int lane, int lmc, int pb) {
    bool kp = (lane & pb) == 0;
#pragma unroll
    for (int oct = 0; oct < 24; oct += 8) {
        float tp[8], tt[8];
#pragma unroll
        for (int i = 0; i < 8; i++) {
            tp[i] = __shfl_xor_sync(FULLM, p[oct + (i ^ 7)], lmc);
            tt[i] = __shfl_xor_sync(FULLM, t[oct + (i ^ 7)], lmc);
        }
#pragma unroll
        for (int i = 0; i < 8; i++) {
            p[oct + i] = kp ? fminf(p[oct + i], tp[i]) : fmaxf(p[oct + i], tp[i]);
            t[oct + i] = kp ? fminf(t[oct + i], tt[i]) : fmaxf(t[oct + i], tt[i]);
        }
    }
}
__device__ __forceinline__ void F256_2(float p[24], float t[24]) {
#pragma unroll
    for (int h = 0; h < 2; h++) {
        int base = h ? 4 : 0;
        float a1[4], a2[4], b1[4], b2[4];
#pragma unroll
        for (int i = 0; i < 4; i++) {
            a1[i] = __shfl_xor_sync(FULLM, p[15 - (base + i)], 15);
            a2[i] = __shfl_xor_sync(FULLM, p[base + i], 15);
            b1[i] = __shfl_xor_sync(FULLM, t[15 - (base + i)], 15);
            b2[i] = __shfl_xor_sync(FULLM, t[base + i], 15);
        }
#pragma unroll
        for (int i = 0; i < 4; i++) {
            p[base + i]        = fminf(p[base + i], a1[i]);
            p[15 - (base + i)] = fmaxf(p[15 - (base + i)], a2[i]);
            t[base + i]        = fminf(t[base + i], b1[i]);
            t[15 - (base + i)] = fmaxf(t[15 - (base + i)], b2[i]);
        }
    }
}

__device__ __forceinline__ void bsort2runs_2(float p[24], float t[24], int lane) {
    sort8_2(p, t); sort8_2(p + 8, t + 8); sort8_2(p + 16, t + 16);
    FL2(p,t,lane,1,1);  P4_2(p,t); P2_2(p,t); P1_2(p,t);                 // k=16
    FL2(p,t,lane,3,2);  CR2(p,t,lane,1);
    P4_2(p,t); P2_2(p,t); P1_2(p,t);                                     // k=32
    FL2(p,t,lane,7,4);  CR2(p,t,lane,2); CR2(p,t,lane,1);
    P4_2(p,t); P2_2(p,t); P1_2(p,t);                                     // k=64
    FL2(p,t,lane,15,8); CR2(p,t,lane,4); CR2(p,t,lane,2); CR2(p,t,lane,1);
    P4_2(p,t); P2_2(p,t); P1_2(p,t);                                     // k=128
    F256_2(p,t); CRh2(p,t,lane,8); CRh2(p,t,lane,4); CRh2(p,t,lane,2);
    CRh2(p,t,lane,1); P4h2(p,t); P2h2(p,t); P1h2(p,t);                   // k=256
}

// select rank k (1-based) from sorted A (m) + sorted B (n); slot g at
// base[g + (g>>5)], B at slots boff+g. 9 guarded bisection steps.
__device__ __forceinline__ float kth2(const float* base, int boff, int m, int n, int k) {
    int lo = max(0, k - n), hi = min(k, m);
#pragma unroll
    for (int it = 0; it < 9; it++) {
        int i  = (lo + hi + 1) >> 1;
        int ia = max(i - 1, 0);
        float Av = base[ia + (ia >> 5)];
        int j = k - i;
        int gb = boff + j;
        float Bv = (j < n) ? base[gb + (gb >> 5)] : POSINF;
        if (lo < hi) { if (Av <= Bv) lo = i; else hi = i - 1; }
    }
    int i = lo, j = k - lo;
    int ia = i - 1, jb = j - 1;
    float av = NEGINF, bv = NEGINF;
    if (i > 0) av = base[ia + (ia >> 5)];
    if (j > 0 && jb < n) { int gb = boff + jb; bv = base[gb + (gb >> 5)]; }
    return fmaxf(av, bv);
}

// ====== dual bitonic-to-2-runs for 512 slots, lane-major (k_theil) ===========
__device__ __forceinline__ void bsort2runs512_2(float p[16], float t[16], int lane) {
#pragma unroll
    for (int k = 2; k <= 16; k <<= 1) {
#pragma unroll
        for (int r = 0; r < 16; r++)
            if ((r & (k - 1)) < (k >> 1)) csw2(p[r],p[r^(k-1)],t[r],t[r^(k-1)]);
#pragma unroll
        for (int j = 8; j >= 1; j >>= 1)
            if (j <= (k >> 2)) {
#pragma unroll
                for (int r = 0; r < 16; r++)
                    if ((r & j) == 0) csw2(p[r],p[r|j],t[r],t[r|j]);
            }
    }
#pragma unroll
    for (int k = 32; k <= 256; k <<= 1) {
        {
            int  lm      = (k - 1) >> 4;
            bool keepmin = ((lane & (k >> 5)) == 0);
#pragma unroll
            for (int r = 0; r < 8; r++) {
                float aP = __shfl_xor_sync(FULLM, p[15 - r], lm);
                float bP = __shfl_xor_sync(FULLM, p[r], lm);
                float aT = __shfl_xor_sync(FULLM, t[15 - r], lm);
                float bT = __shfl_xor_sync(FULLM, t[r], lm);
                p[r]      = keepmin ? fminf(p[r], aP)      : fmaxf(p[r], aP);
                p[15 - r] = keepmin ? fminf(p[15 - r], bP) : fmaxf(p[15 - r], bP);
                t[r]      = keepmin ? fminf(t[r], aT)      : fmaxf(t[r], aT);
                t[15 - r] = keepmin ? fminf(t[15 - r], bT) : fmaxf(t[15 - r], bT);
            }
        }
#pragma unroll
        for (int j = 128; j >= 16; j >>= 1)
            if (j <= (k >> 2)) {
                int  lm      = j >> 4;
                bool keepmin = ((lane & lm) == 0);
#pragma unroll
                for (int r = 0; r < 16; r++) {
                    float oP = __shfl_xor_sync(FULLM, p[r], lm);
                    float oT = __shfl_xor_sync(FULLM, t[r], lm);
                    p[r] = keepmin ? fminf(p[r], oP) : fmaxf(p[r], oP);
                    t[r] = keepmin ? fminf(t[r], oT) : fmaxf(t[r], oT);
                }
            }
#pragma unroll
        for (int j = 8; j >= 1; j >>= 1)
            if (j <= (k >> 2)) {
#pragma unroll
                for (int r = 0; r < 16; r++)
                    if ((r & j) == 0) csw2(p[r],p[r|j],t[r],t[r|j]);
            }
    }
}

// ---------------- kernel 0: zero accumulators + build pair tables ------------
__global__ void k_zero() {
    int tid = threadIdx.x;
    if (tid == 0) { g_sse = 0.0; g_trend = 0.0; }
    if (tid < NPAIR) {
        int i = 0, rem = tid, cnt = NY - 1;
        while (rem >= cnt) { rem -= cnt; i++; cnt--; }
        int j = i + 1 + rem;
        g_pairIJ[tid]  = i | (j << 8);
        g_pairInv[tid] = 1.0f / (float)(j - i);
    }
}

// ---------------- kernel 1: transpose + SSE + dual sort-to-runs + select -----
// grid (SGRID/16, NY), block 256; dynamic smem 2*16*SROW*4 bytes.
// (256,3): allow up to 85 regs for the fused dual walk (48 array + temps).
__global__ __launch_bounds__(256, 3) void k_sortdays(const float* __restrict__ pred,
                                                     const float* __restrict__ obs) {
    extern __shared__ float dsm[];
    float* shP = dsm;                       // [16][SROW]
    float* shT = dsm + K1_SER * SROW;
    __shared__ float warpsum[8];

    int y      = blockIdx.y;
    int s_base = blockIdx.x * K1_SER;
    int tid    = threadIdx.x;
    int w      = tid >> 5;
    int lane   = tid & 31;
    int lane4  = lane & 15;

    const float* pbase = pred + (size_t)y * DAYS * SGRID + s_base;
    const float* tbase = obs  + (size_t)y * DAYS * SGRID + s_base;

    // vectorized coalesced load + transpose (day d -> col (d&7)*46+(d>>3)) + SSE
    float sse = 0.0f;
    for (int idx = tid; idx < DAYS * 4; idx += 256) {
        int d  = idx >> 2;
        int q  = (idx & 3) << 2;
        int ad = (d & 7) * 46 + (d >> 3);
        float4 a4 = *(const float4*)(pbase + d * SGRID + q);
        float4 b4 = *(const float4*)(tbase + d * SGRID + q);
        shP[(q + 0) * SROW + ad] = a4.x;  shT[(q + 0) * SROW + ad] = b4.x;
        shP[(q + 1) * SROW + ad] = a4.y;  shT[(q + 1) * SROW + ad] = b4.y;
        shP[(q + 2) * SROW + ad] = a4.z;  shT[(q + 2) * SROW + ad] = b4.z;
        shP[(q + 3) * SROW + ad] = a4.w;  shT[(q + 3) * SROW + ad] = b4.w;
        float dx = a4.x - b4.x, dy = a4.y - b4.y;
        float dz = a4.z - b4.z, dw = a4.w - b4.w;
        sse += dx * dx + dy * dy + dz * dz + dw * dw;
    }
#pragma unroll
    for (int o = 16; o > 0; o >>= 1) sse += __shfl_down_sync(FULLM, sse, o);
    if (lane == 0) warpsum[w] = sse;
    __syncthreads();
    if (tid == 0) {
        float tot = 0.0f;
#pragma unroll
        for (int i = 0; i < 8; i++) tot += warpsum[i];
        atomicAdd(&g_sse, (double)tot);
    }

    int sidx = 2 * w + (lane >> 4);     // this half-warp's series (0..15)
    int s    = s_base + sidx;
    float* rowP = shP + sidx * SROW;
    float* rowT = shT + sidx * SROW;

    // load both streams: reg r holds slot g = (r&7) | (lane4<<3) | ((r>>3)<<7)
    float vP[24], vT[24];
    float msP = 0.0f, msT = 0.0f;
#pragma unroll
    for (int r = 0; r < 24; r++) {
        int lo3 = r & 7, hi2 = r >> 3;
        int g   = lo3 | (lane4 << 3) | (hi2 << 7);
        int ad  = lo3 * 46 + lane4 + (hi2 << 4);
        if (g < DAYS) {
            vP[r] = rowP[ad]; msP += vP[r];
            vT[r] = rowT[ad]; msT += vT[r];
        } else {
            vP[r] = POSINF;
            vT[r] = POSINF;
        }
    }
#pragma unroll
    for (int o = 8; o > 0; o >>= 1) {
        msP += __shfl_xor_sync(FULLM, msP, o);
        msT += __shfl_xor_sync(FULLM, msT, o);
    }
    if (lane4 == 0) {
        g_pM[s * NY + y] = msP * (1.0f / (float)DAYS);
        g_tM[s * NY + y] = msT * (1.0f / (float)DAYS);
    }

    bsort2runs_2(vP, vT, lane);

    // dump both sorted-run sets: slot g -> row[g + (g>>5)]
#pragma unroll
    for (int r = 0; r < 24; r++) {
        int g = (r & 7) | (lane4 << 3) | ((r >> 3) << 7);
        int a = g + (g >> 5);
        rowP[a] = vP[r];
        rowT[a] = vT[r];
    }
    __syncwarp();

    // lanes 0..4 select P ranks, lanes 5..9 select T ranks
    int rq = (lane4 < NQ) ? lane4 : lane4 - NQ;
    int R  = rq == 0 ? 364 : rq == 1 ? 357 : rq == 2 ? 182 : rq == 3 ? 109 : 7;
    const float* base = (lane4 < NQ) ? rowP : rowT;
    float ans = kth2(base, 256, 256, 128, R + 1);
    if (lane4 < NQ)               g_pQ[(s * NQ + rq) * NY + y] = ans;
    else if (lane4 < 2 * NQ)      g_tQ[(s * NQ + rq) * NY + y] = ans;
}

// ---------------- kernel 2: Theil-Sen medians + trend terms ------------------
// grid SGRID, block 192 (6 warps: warp0 = mean, warps 1..5 = quantiles)
__global__ __launch_bounds__(192, 5) void k_theil() {
    __shared__ float xs[6][2][NY];
    __shared__ float scr[6][2][528];    // 512 slots + (g>>5) padding

    int s    = blockIdx.x;
    int w    = threadIdx.x >> 5;
    int lane = threadIdx.x & 31;

    const float* xp;
    const float* xt;
    if (w == 0) { xp = g_pM + s * NY;                  xt = g_tM + s * NY; }
    else        { xp = g_pQ + (s * NQ + (w - 1)) * NY; xt = g_tQ + (s * NQ + (w - 1)) * NY; }
    if (lane < NY) {
        xs[w][0][lane] = xp[lane];
        xs[w][1][lane] = xt[lane];
    }
    __syncwarp();

    float vP[16], vT[16];
#pragma unroll
    for (int r = 0; r < 16; r++) {
        int p = (r << 5) | lane;   // arbitrary pair->slot map (median is set-invariant)
        if (p < NPAIR) {
            int   ij  = g_pairIJ[p];
            float inv = g_pairInv[p];
            int i = ij & 255, j = ij >> 8;
            vP[r] = (xs[w][0][j] - xs[w][0][i]) * inv;
            vT[r] = (xs[w][1][j] - xs[w][1][i]) * inv;
        } else {
            vP[r] = POSINF;
            vT[r] = POSINF;
        }
    }

    bsort2runs512_2(vP, vT, lane);   // each: two sorted 256-runs

#pragma unroll
    for (int r = 0; r < 16; r++) {
        int g = (lane << 4) | r;
        int a = g + (g >> 5);
        scr[w][0][a] = vP[r];
        scr[w][1][a] = vT[r];
    }
    __syncwarp();

    // lane 0 selects median (rank 217, k=218) of P, lane 1 of T
    const float* base = (lane == 1) ? &scr[w][1][0] : &scr[w][0][0];
    float ans = kth2(base, 256, 256, 256, 218);
    float sp = __shfl_sync(FULLM, ans, 0);
    float st = __shfl_sync(FULLM, ans, 1);

    if (lane == 0) {
        double term;
        if (w == 0) { float d = st - sp;   term = (double)d * (double)d; }
        else        { float q = st / (-sp); term = (double)q * (double)q; }
        atomicAdd(&g_trend, term);
    }
}

// ---------------- kernel 3: finalize -----------------------------------------
__global__ void k_final(float* out) {
    double mse = g_sse / ((double)TT * (double)SGRID);
    out[0] = (float)(sqrt(mse) + g_trend / (double)SGRID);
}

// ---------------- launch ------------------------------------------------------
extern "C" void kernel_launch(void* const* d_in, const int* in_sizes, int n_in,
                              void* d_out, int out_size) {
    const float* y_pred = (const float*)d_in[0];
    const float* y_obs  = (const float*)d_in[1];
    float* out = (float*)d_out;

    const int dyn = 2 * K1_SER * SROW * (int)sizeof(float);  // 50,816 B
    cudaFuncSetAttribute(k_sortdays, cudaFuncAttributeMaxDynamicSharedMemorySize, dyn);

    k_zero<<<1, 512>>>();
    k_sortdays<<<dim3(SGRID / K1_SER, NY), 256, dyn>>>(y_pred, y_obs);
    k_theil<<<SGRID, 192>>>();
    k_final<<<1, 1>>>(out);
}